// round 3
// baseline (speedup 1.0000x reference)
#include <cuda_runtime.h>
#include <cuda_bf16.h>

// Problem constants (fixed by the reference: pc (4,4096,3), mask (4,4096,30))
#define BQ_B 4
#define BQ_N 4096
#define BQ_C 30
#define BQ_K 16
#define BQ_R2 0.04f

#define WARPS_PER_BLOCK 8
#define NUM_QUERIES (BQ_B * BQ_N)                       // 16384
#define NUM_BLOCKS (NUM_QUERIES / WARPS_PER_BLOCK)      // 2048

__device__ float g_partials[NUM_BLOCKS];

__global__ __launch_bounds__(WARPS_PER_BLOCK * 32)
void ballq_loss_kernel(const float* __restrict__ pc,
                       const float* __restrict__ mask) {
    const int warp = threadIdx.x >> 5;
    const int lane = threadIdx.x & 31;
    const int q = blockIdx.x * WARPS_PER_BLOCK + warp;   // query id, 0..16383
    const int b = q >> 12;                               // q / 4096
    const int n = q & (BQ_N - 1);                        // q % 4096

    const float* __restrict__ pcb = pc + (size_t)b * BQ_N * 3;

    // Query point (broadcast load, same address across warp)
    const float qx = pcb[n * 3 + 0];
    const float qy = pcb[n * 3 + 1];
    const float qz = pcb[n * 3 + 2];
    const float qsq = qx * qx + qy * qy + qz * qz;

    __shared__ int sidx[WARPS_PER_BLOCK][BQ_K];

    // ---- Ball-query scan: first K indices (in index order) with d2 < R2 ----
    // d2 computed with the reference's algebraic form (sq_n + sq_m - 2*dot)
    // so boundary rounding errors correlate with the reference.
    int cnt = 0;  // uniform across the warp
    for (int base = 0; base < BQ_N && cnt < BQ_K; base += 32) {
        const int m = base + lane;                       // N % 32 == 0, always valid
        const float mx = pcb[m * 3 + 0];
        const float my = pcb[m * 3 + 1];
        const float mz = pcb[m * 3 + 2];
        const float msq = mx * mx + my * my + mz * mz;
        const float dot = qx * mx + qy * my + qz * mz;
        const float d2 = qsq + msq - 2.0f * dot;
        unsigned bal = __ballot_sync(0xffffffffu, d2 < BQ_R2);
        // Uniform bit-peel: lowest set bit = smallest index
        while (bal && cnt < BQ_K) {
            const int l = __ffs(bal) - 1;
            if (lane == 0) sidx[warp][cnt] = base + l;
            cnt++;
            bal &= bal - 1;
        }
    }
    // Pad remaining slots with the first found index (cnt >= 1 always: self hit)
    if (lane == 0) {
        const int f = sidx[warp][0];
        for (int j = cnt; j < BQ_K; j++) sidx[warp][j] = f;
    }
    __syncwarp();

    // ---- Loss: lane c handles channel c (c < 30); neighbor rows coalesced ----
    float acc = 0.0f;
    if (lane < BQ_C) {
        const float* __restrict__ mb = mask + (size_t)b * BQ_N * BQ_C;
        const float mq = mb[n * BQ_C + lane];
#pragma unroll
        for (int j = 0; j < BQ_K; j++) {
            const int id = sidx[warp][j];
            acc += fabsf(mq - mb[id * BQ_C + lane]);
        }
    }
    // Warp reduce (lanes 30,31 contribute 0)
#pragma unroll
    for (int off = 16; off; off >>= 1)
        acc += __shfl_down_sync(0xffffffffu, acc, off);

    __shared__ float wl[WARPS_PER_BLOCK];
    if (lane == 0) wl[warp] = acc;
    __syncthreads();
    if (threadIdx.x == 0) {
        float s = 0.0f;
#pragma unroll
        for (int w = 0; w < WARPS_PER_BLOCK; w++) s += wl[w];
        g_partials[blockIdx.x] = s;  // deterministic: fixed order, no atomics
    }
}

__global__ __launch_bounds__(256)
void ballq_reduce_kernel(float* __restrict__ out) {
    __shared__ float sh[256];
    float s = 0.0f;
    for (int i = threadIdx.x; i < NUM_BLOCKS; i += 256)
        s += g_partials[i];
    sh[threadIdx.x] = s;
    __syncthreads();
#pragma unroll
    for (int off = 128; off; off >>= 1) {
        if (threadIdx.x < off) sh[threadIdx.x] += sh[threadIdx.x + off];
        __syncthreads();
    }
    if (threadIdx.x == 0)
        out[0] = sh[0] * (1.0f / ((float)BQ_K * (float)NUM_QUERIES));
}

extern "C" void kernel_launch(void* const* d_in, const int* in_sizes, int n_in,
                              void* d_out, int out_size) {
    const float* pc   = (const float*)d_in[0];   // (4, 4096, 3) float32
    const float* mask = (const float*)d_in[1];   // (4, 4096, 30) float32
    float* out = (float*)d_out;                  // scalar float32

    ballq_loss_kernel<<<NUM_BLOCKS, WARPS_PER_BLOCK * 32>>>(pc, mask);
    ballq_reduce_kernel<<<1, 256>>>(out);
}

// round 4
// speedup vs baseline: 1.3683x; 1.3683x over previous
#include <cuda_runtime.h>
#include <cuda_bf16.h>

// Problem constants (fixed by the reference: pc (4,4096,3), mask (4,4096,30))
#define BQ_B 4
#define BQ_N 4096
#define BQ_C 30
#define BQ_K 16
#define BQ_R2 0.04f

#define WARPS_PER_BLOCK 8
#define NUM_QUERIES (BQ_B * BQ_N)                       // 16384
#define NUM_BLOCKS (NUM_QUERIES / WARPS_PER_BLOCK)      // 2048

__device__ float g_partials[NUM_BLOCKS];
__device__ unsigned g_ticket = 0;   // reset by the last block each launch

__global__ __launch_bounds__(WARPS_PER_BLOCK * 32)
void ballq_loss_kernel(const float* __restrict__ pc,
                       const float* __restrict__ mask,
                       float* __restrict__ out) {
    const int warp = threadIdx.x >> 5;
    const int lane = threadIdx.x & 31;
    const int q = blockIdx.x * WARPS_PER_BLOCK + warp;   // query id, 0..16383
    const int b = q >> 12;                               // q / 4096
    const int n = q & (BQ_N - 1);                        // q % 4096

    const float* __restrict__ pcb = pc + (size_t)b * BQ_N * 3;

    // Query point (broadcast load, same address across warp)
    const float qx = pcb[n * 3 + 0];
    const float qy = pcb[n * 3 + 1];
    const float qz = pcb[n * 3 + 2];
    const float qsq = qx * qx + qy * qy + qz * qz;

    __shared__ int sidx[WARPS_PER_BLOCK][BQ_K];

    // ---- Ball-query scan: first K indices (in index order) with d2 < R2 ----
    // 128 candidates per iteration: all 12 loads issued before any ballot
    // (MLP ~12), index order preserved via m = base + j*32 + lane.
    // d2 uses the reference's algebraic form (qsq + msq - 2*dot) so boundary
    // rounding errors correlate with the reference.
    int cnt = 0;  // uniform across the warp
    for (int base = 0; base < BQ_N && cnt < BQ_K; base += 128) {
        float d2[4];
#pragma unroll
        for (int j = 0; j < 4; j++) {
            const int m = base + j * 32 + lane;          // N % 128 == 0, always valid
            const float mx = pcb[m * 3 + 0];
            const float my = pcb[m * 3 + 1];
            const float mz = pcb[m * 3 + 2];
            const float msq = mx * mx + my * my + mz * mz;
            const float dot = qx * mx + qy * my + qz * mz;
            d2[j] = qsq + msq - 2.0f * dot;
        }
#pragma unroll
        for (int j = 0; j < 4; j++) {
            if (cnt < BQ_K) {                            // uniform predicate
                unsigned bal = __ballot_sync(0xffffffffu, d2[j] < BQ_R2);
                // Uniform bit-peel: lowest set bit = smallest index
                while (bal && cnt < BQ_K) {
                    const int l = __ffs(bal) - 1;
                    if (lane == 0) sidx[warp][cnt] = base + j * 32 + l;
                    cnt++;
                    bal &= bal - 1;
                }
            }
        }
    }
    // Pad remaining slots with the first found index (cnt >= 1 always: self hit)
    if (lane == 0) {
        const int f = sidx[warp][0];
        for (int j = cnt; j < BQ_K; j++) sidx[warp][j] = f;
    }
    __syncwarp();

    // ---- Loss: lane c handles channel c (c < 30); neighbor rows coalesced ----
    float acc = 0.0f;
    if (lane < BQ_C) {
        const float* __restrict__ mb = mask + (size_t)b * BQ_N * BQ_C;
        const float mq = mb[n * BQ_C + lane];
#pragma unroll
        for (int j = 0; j < BQ_K; j++) {
            const int id = sidx[warp][j];
            acc += fabsf(mq - mb[id * BQ_C + lane]);
        }
    }
    // Warp reduce (lanes 30,31 contribute 0)
#pragma unroll
    for (int off = 16; off; off >>= 1)
        acc += __shfl_down_sync(0xffffffffu, acc, off);

    __shared__ float wl[WARPS_PER_BLOCK];
    if (lane == 0) wl[warp] = acc;
    __syncthreads();

    // Per-block partial in fixed order (no float atomics -> deterministic)
    __shared__ bool is_last;
    if (threadIdx.x == 0) {
        float s = 0.0f;
#pragma unroll
        for (int w = 0; w < WARPS_PER_BLOCK; w++) s += wl[w];
        g_partials[blockIdx.x] = s;
        __threadfence();                                  // publish partial
        unsigned t = atomicAdd(&g_ticket, 1u);            // int ticket only
        is_last = (t == NUM_BLOCKS - 1);
    }
    __syncthreads();

    // ---- Fused final reduction: last block, fixed order, deterministic ----
    if (is_last) {
        __shared__ float sh[256];
        float s = 0.0f;
        for (int i = threadIdx.x; i < NUM_BLOCKS; i += 256)
            s += g_partials[i];
        sh[threadIdx.x] = s;
        __syncthreads();
#pragma unroll
        for (int off = 128; off; off >>= 1) {
            if (threadIdx.x < off) sh[threadIdx.x] += sh[threadIdx.x + off];
            __syncthreads();
        }
        if (threadIdx.x == 0) {
            out[0] = sh[0] * (1.0f / ((float)BQ_K * (float)NUM_QUERIES));
            g_ticket = 0;                                 // reset for next replay
        }
    }
}

extern "C" void kernel_launch(void* const* d_in, const int* in_sizes, int n_in,
                              void* d_out, int out_size) {
    const float* pc   = (const float*)d_in[0];   // (4, 4096, 3) float32
    const float* mask = (const float*)d_in[1];   // (4, 4096, 30) float32
    float* out = (float*)d_out;                  // scalar float32

    ballq_loss_kernel<<<NUM_BLOCKS, WARPS_PER_BLOCK * 32>>>(pc, mask, out);
}